// round 2
// baseline (speedup 1.0000x reference)
#include <cuda_runtime.h>
#include <cuda_bf16.h>
#include <math.h>

// Problem constants
#define BB 128
#define TT 256
#define DD 256
#define HH 256

#define NBLK 128        // k_seq grid: 16 clusters x 8 CTAs
#define CLU  8          // cluster size (portable max)

// ---------------- device scratch ----------------
__device__ float g_pre1[TT * BB * HH];       // pre1[t][b][h] = x_t @ Wih1_t + b1_t
__device__ float g_h1[2][BB * HH];
__device__ float g_h2[2][BB * HH];
__device__ float g_h1bk[BB * HH];
__device__ float g_h2bk[BB * HH];

// ---------------- reset kernel (per-replay determinism) ----------------
__global__ void k_reset() {
    unsigned i = blockIdx.x * blockDim.x + threadIdx.x;
    for (unsigned j = i; j < BB * HH; j += gridDim.x * blockDim.x) {
        g_h1[0][j] = 0.f;
        g_h2[0][j] = 0.f;
    }
}

// ---------------- generic 64x64 register-blocked fp32 GEMM tile ----------------
__device__ __forceinline__ void gemm64_body(
    const float* __restrict__ A, long lda,
    const float* __restrict__ A2, int ksplit, long lda2,
    const float* __restrict__ W, long ldw, int wtrans,
    const float* __restrict__ bias,
    float* __restrict__ C, long ldc,
    int K, int row0, int col0, int act,
    float* sA, float* sW)
{
    const int tid = threadIdx.x;
    const int tx = tid & 15;
    const int ty = tid >> 4;
    float acc[4][4];
#pragma unroll
    for (int i = 0; i < 4; i++)
#pragma unroll
        for (int j = 0; j < 4; j++) acc[i][j] = 0.f;

#pragma unroll 1
    for (int k0 = 0; k0 < K; k0 += 64) {
        const float* Ak = A; long ldak = lda; int kb = k0;
        if (A2 != nullptr && k0 >= ksplit) { Ak = A2; ldak = lda2; kb = k0 - ksplit; }

        __syncthreads();
#pragma unroll
        for (int p = 0; p < 4; p++) {
            int i = p * 256 + tid;
            int rr = i >> 4;
            int k4 = i & 15;
            float4 v = *(const float4*)(Ak + (long)(row0 + rr) * ldak + kb + k4 * 4);
            *(float4*)(sA + rr * 68 + k4 * 4) = v;
        }
        if (!wtrans) {
#pragma unroll
            for (int p = 0; p < 16; p++) {
                int i = p * 256 + tid;
                int kk = i >> 6, cc = i & 63;
                sW[kk * 68 + cc] = W[(long)(k0 + kk) * ldw + col0 + cc];
            }
        } else {
#pragma unroll
            for (int p = 0; p < 16; p++) {
                int i = p * 256 + tid;
                int kk = i & 63, cc = i >> 6;
                sW[kk * 68 + cc] = W[(long)(col0 + cc) * ldw + k0 + kk];
            }
        }
        __syncthreads();

#pragma unroll
        for (int k = 0; k < 64; k++) {
            float a0 = sA[(ty * 4 + 0) * 68 + k];
            float a1 = sA[(ty * 4 + 1) * 68 + k];
            float a2 = sA[(ty * 4 + 2) * 68 + k];
            float a3 = sA[(ty * 4 + 3) * 68 + k];
            float4 wv = *(const float4*)(sW + k * 68 + tx * 4);
            acc[0][0] = fmaf(a0, wv.x, acc[0][0]);
            acc[0][1] = fmaf(a0, wv.y, acc[0][1]);
            acc[0][2] = fmaf(a0, wv.z, acc[0][2]);
            acc[0][3] = fmaf(a0, wv.w, acc[0][3]);
            acc[1][0] = fmaf(a1, wv.x, acc[1][0]);
            acc[1][1] = fmaf(a1, wv.y, acc[1][1]);
            acc[1][2] = fmaf(a1, wv.z, acc[1][2]);
            acc[1][3] = fmaf(a1, wv.w, acc[1][3]);
            acc[2][0] = fmaf(a2, wv.x, acc[2][0]);
            acc[2][1] = fmaf(a2, wv.y, acc[2][1]);
            acc[2][2] = fmaf(a2, wv.z, acc[2][2]);
            acc[2][3] = fmaf(a2, wv.w, acc[2][3]);
            acc[3][0] = fmaf(a3, wv.x, acc[3][0]);
            acc[3][1] = fmaf(a3, wv.y, acc[3][1]);
            acc[3][2] = fmaf(a3, wv.z, acc[3][2]);
            acc[3][3] = fmaf(a3, wv.w, acc[3][3]);
        }
    }

#pragma unroll
    for (int i = 0; i < 4; i++) {
#pragma unroll
        for (int j = 0; j < 4; j++) {
            int rr = row0 + ty * 4 + i;
            int cc = col0 + tx * 4 + j;
            float v = acc[i][j] + bias[cc];
            if (act) v = tanhf(v);
            C[(long)rr * ldc + cc] = v;
        }
    }
}

// ---------------- K1: precompute pre1[t] = x_t @ Wih_f[0,t] + b_f[0,t] ----------------
__global__ __launch_bounds__(256) void k_pre(
    const float* __restrict__ x, const float* __restrict__ Wih_f,
    const float* __restrict__ b_f)
{
    __shared__ float sA[64 * 68];
    __shared__ float sW[64 * 68];
    int t = blockIdx.y;
    int tile = blockIdx.x;
    int row0 = (tile >> 2) * 64;
    int col0 = (tile & 3) * 64;
    gemm64_body(x + (long)t * DD, (long)TT * DD,
                nullptr, 1 << 30, 0,
                Wih_f + (long)t * DD * HH, HH, 0,
                b_f + (long)t * HH,
                g_pre1 + (long)t * BB * HH, HH,
                DD, row0, col0, /*act=*/0, sA, sW);
}

// ================= K2: persistent sequential scan, 8-CTA clusters =================
// Cluster g owns batch rows [8g, 8g+8); CTA rank r owns cols [32r, 32r+32).
// Thread (s = tid>>5, c = tid&31): split-K slice s (k in [32s,32s+32)), column c.
// Weights live in registers (coalesced LDG, prefetched during previous phase).
// Shared h loads are warp-uniform broadcasts. Split-K reduced through smem.

__device__ __forceinline__ void csync() {
    asm volatile("barrier.cluster.arrive.aligned;" ::: "memory");
    asm volatile("barrier.cluster.wait.aligned;" ::: "memory");
}

__device__ __forceinline__ void stage_hs(float* hs, const float* __restrict__ src,
                                         int row_base, int tid) {
#pragma unroll
    for (int p = 0; p < 2; p++) {
        int i = p * 256 + tid;
        int rr = i >> 6;
        int c4 = i & 63;
        float4 v = __ldcg((const float4*)(src + (long)(row_base + rr) * HH) + c4);
        *((float4*)(hs + rr * HH) + c4) = v;
    }
}

// prefetch weight slice: w[j] = W[(32s+j)][col0+c]  (coalesced across warp per j)
__device__ __forceinline__ void pf_w(float (&w)[32], const float* __restrict__ W,
                                     int s, int c, int col0) {
    const float* p = W + (long)(s * 32) * HH + col0 + c;
#pragma unroll
    for (int j = 0; j < 32; j++) w[j] = __ldg(p + (long)j * HH);
}

__device__ __forceinline__ void compute_dot(const float* hs, const float (&w)[32],
                                            int s, float (&acc)[8]) {
#pragma unroll
    for (int r = 0; r < 8; r++) acc[r] = 0.f;
#pragma unroll
    for (int i = 0; i < 8; i++) {
        float4 hv[8];
#pragma unroll
        for (int r = 0; r < 8; r++)
            hv[r] = *((const float4*)(hs + r * HH + s * 32 + i * 4));  // uniform bcast
#pragma unroll
        for (int r = 0; r < 8; r++) {
            acc[r] = fmaf(hv[r].x, w[i * 4 + 0], acc[r]);
            acc[r] = fmaf(hv[r].y, w[i * 4 + 1], acc[r]);
            acc[r] = fmaf(hv[r].z, w[i * 4 + 2], acc[r]);
            acc[r] = fmaf(hv[r].w, w[i * 4 + 3], acc[r]);
        }
    }
}

__device__ __forceinline__ float reduce_partials(float* red, const float (&acc)[8],
                                                 int s, int c) {
#pragma unroll
    for (int r = 0; r < 8; r++) red[s * 256 + r * 32 + c] = acc[r];
    __syncthreads();
    // thread's output element: row = s, col = c (within block tile)
    float v = 0.f;
#pragma unroll
    for (int q = 0; q < 8; q++) v += red[q * 256 + s * 32 + c];
    return v;
}

// one dot phase: stage h rows, prefetch next weights, compute, split-K reduce
__device__ __forceinline__ float phase_dot(
    float* hs, float* red,
    const float* __restrict__ h_src, int row_base,
    const float (&wu)[32], float (&wp)[32], const float* __restrict__ pfW,
    int s, int c, int col0, int tid)
{
    stage_hs(hs, h_src, row_base, tid);
    __syncthreads();
    pf_w(wp, pfW, s, c, col0);         // overlap prefetch with compute
    float acc[8];
    compute_dot(hs, wu, s, acc);
    return reduce_partials(red, acc, s, c);
}

__global__ __launch_bounds__(256, 1) __cluster_dims__(CLU, 1, 1)
void k_seq(const float* __restrict__ Wih_f, const float* __restrict__ Whh_f,
           const float* __restrict__ b_f)
{
    __shared__ float hs[8 * HH];      // 8 KB
    __shared__ float red[8 * 256];    // 8 KB
    const int tid = threadIdx.x;
    const int s = tid >> 5;
    const int c = tid & 31;
    const int grp = blockIdx.x >> 3;
    const int rank = blockIdx.x & 7;
    const int row_base = grp * 8;
    const int col0 = rank * 32;
    const int out_off = (row_base + s) * HH + col0 + c;

    const float* Whh1 = Whh_f;
    const float* Wih2 = Wih_f + (long)TT * DD * HH;
    const float* Whh2 = Whh_f + (long)TT * HH * HH;
    const float* b2   = b_f + (long)TT * HH;

    float wX[32], wY[32];
    pf_w(wX, Whh1, s, c, col0);       // Whh1[t=0]

#define STEP(WA, WB, t, pp)                                                         \
    {                                                                               \
        int tn = (t) < TT - 1 ? (t) + 1 : TT - 1;                                   \
        /* phase A: h1_new = tanh(pre1[t] + h1_prev @ Whh1[t]) */                   \
        float dA = phase_dot(hs, red, g_h1[pp], row_base, WA, WB,                   \
                             Wih2 + (long)(t) * DD * HH, s, c, col0, tid);          \
        float pre = __ldg(g_pre1 + (long)(t) * BB * HH + out_off);                  \
        float h1v = tanhf(pre + dA);                                                \
        __stcg(g_h1[(pp) ^ 1] + out_off, h1v);                                      \
        __threadfence();                                                            \
        csync();                                                                    \
        /* phase B1: acc2 = b2[t] + h1_new @ Wih2[t] */                             \
        float d1 = phase_dot(hs, red, g_h1[(pp) ^ 1], row_base, WB, WA,             \
                             Whh2 + (long)(t) * HH * HH, s, c, col0, tid);          \
        float acc2 = __ldg(b2 + (long)(t) * HH + col0 + c) + d1;                    \
        /* phase B2: acc2 += h2_prev @ Whh2[t] */                                   \
        float d2 = phase_dot(hs, red, g_h2[pp], row_base, WA, WB,                   \
                             Whh1 + (long)tn * HH * HH, s, c, col0, tid);           \
        acc2 += d2;                                                                 \
        float h2v = tanhf(acc2);                                                    \
        __stcg(g_h2[(pp) ^ 1] + out_off, h2v);                                      \
        __threadfence();                                                            \
        csync();                                                                    \
    }

#pragma unroll 1
    for (int t2 = 0; t2 < TT; t2 += 2) {
        STEP(wX, wY, t2, 0);          // t even: pp = 0
        STEP(wY, wX, t2 + 1, 1);      // t odd:  pp = 1
    }
#undef STEP
}

// ---------------- tail kernels: backward single step + fc head ----------------
__global__ __launch_bounds__(256) void k_tail_a(
    const float* __restrict__ x, const float* __restrict__ Wih_b,
    const float* __restrict__ b_b)
{
    __shared__ float sA[64 * 68];
    __shared__ float sW[64 * 68];
    int tile = blockIdx.x;
    int row0 = (tile >> 2) * 64, col0 = (tile & 3) * 64;
    gemm64_body(x + (long)(TT - 1) * DD, (long)TT * DD,
                nullptr, 1 << 30, 0,
                Wih_b + (long)(TT - 1) * DD * HH, HH, 0,
                b_b + (long)(TT - 1) * HH,
                g_h1bk, HH, DD, row0, col0, /*act=*/1, sA, sW);
}

__global__ __launch_bounds__(256) void k_tail_b(
    const float* __restrict__ Wih_b, const float* __restrict__ b_b)
{
    __shared__ float sA[64 * 68];
    __shared__ float sW[64 * 68];
    int tile = blockIdx.x;
    int row0 = (tile >> 2) * 64, col0 = (tile & 3) * 64;
    gemm64_body(g_h1bk, HH,
                nullptr, 1 << 30, 0,
                Wih_b + (long)(TT + TT - 1) * DD * HH, HH, 0,
                b_b + (long)(TT + TT - 1) * HH,
                g_h2bk, HH, HH, row0, col0, /*act=*/1, sA, sW);
}

__global__ __launch_bounds__(256) void k_tail_c(
    const float* __restrict__ fc_w, const float* __restrict__ fc_b,
    float* __restrict__ out)
{
    __shared__ float sA[64 * 68];
    __shared__ float sW[64 * 68];
    int tile = blockIdx.x;
    int row0 = (tile >> 2) * 64, col0 = (tile & 3) * 64;
    // h2 forward final state lives in g_h2[0] (T=256 even)
    gemm64_body(g_h2[0], HH,
                g_h2bk, /*ksplit=*/HH, HH,
                fc_w, 2 * HH, /*wtrans=*/1,
                fc_b,
                out, HH, 2 * HH, row0, col0, /*act=*/0, sA, sW);
}

// ---------------- launcher ----------------
extern "C" void kernel_launch(void* const* d_in, const int* in_sizes, int n_in,
                              void* d_out, int out_size) {
    const float* x     = (const float*)d_in[0];
    const float* Wih_f = (const float*)d_in[1];
    const float* Whh_f = (const float*)d_in[2];
    const float* b_f   = (const float*)d_in[3];
    const float* Wih_b = (const float*)d_in[4];
    // d_in[5] = Whh_b: unused (backward output at t=T-1 starts from h0=0)
    const float* b_b   = (const float*)d_in[6];
    const float* fc_w  = (const float*)d_in[7];
    const float* fc_b  = (const float*)d_in[8];
    float* out = (float*)d_out;
    (void)in_sizes; (void)n_in; (void)out_size;

    k_reset<<<32, 256>>>();
    k_pre<<<dim3(8, TT), 256>>>(x, Wih_f, b_f);
    k_seq<<<NBLK, 256>>>(Wih_f, Whh_f, b_f);
    k_tail_a<<<8, 256>>>(x, Wih_b, b_b);
    k_tail_b<<<8, 256>>>(Wih_b, b_b);
    k_tail_c<<<8, 256>>>(fc_w, fc_b, out);
}

// round 3
// speedup vs baseline: 1.7803x; 1.7803x over previous
#include <cuda_runtime.h>
#include <cuda_bf16.h>
#include <math.h>

// Problem constants
#define BB 128
#define TT 256
#define DD 256
#define HH 256

#define NBLK 128        // k_seq grid: 16 row-groups x 8 col-groups (one wave, <=148 SMs)

// ---------------- device scratch ----------------
__device__ float g_pre1[TT * BB * HH];       // pre1[t][b][h] = x_t @ Wih1_t + b1_t
__device__ float g_h1[2][BB * HH];
__device__ float g_h2[2][BB * HH];
__device__ float g_h1bk[BB * HH];
__device__ float g_h2bk[BB * HH];
__device__ unsigned g_cnt;                   // grid barrier counter

// ---------------- reset kernel (per-replay determinism) ----------------
__global__ void k_reset() {
    unsigned i = blockIdx.x * blockDim.x + threadIdx.x;
    if (i == 0) g_cnt = 0u;
    for (unsigned j = i; j < BB * HH; j += gridDim.x * blockDim.x) {
        g_h1[0][j] = 0.f;
        g_h2[0][j] = 0.f;
    }
}

// ---------------- generic 64x64 register-blocked fp32 GEMM tile ----------------
__device__ __forceinline__ void gemm64_body(
    const float* __restrict__ A, long lda,
    const float* __restrict__ A2, int ksplit, long lda2,
    const float* __restrict__ W, long ldw, int wtrans,
    const float* __restrict__ bias,
    float* __restrict__ C, long ldc,
    int K, int row0, int col0, int act,
    float* sA, float* sW)
{
    const int tid = threadIdx.x;
    const int tx = tid & 15;
    const int ty = tid >> 4;
    float acc[4][4];
#pragma unroll
    for (int i = 0; i < 4; i++)
#pragma unroll
        for (int j = 0; j < 4; j++) acc[i][j] = 0.f;

#pragma unroll 1
    for (int k0 = 0; k0 < K; k0 += 64) {
        const float* Ak = A; long ldak = lda; int kb = k0;
        if (A2 != nullptr && k0 >= ksplit) { Ak = A2; ldak = lda2; kb = k0 - ksplit; }

        __syncthreads();
#pragma unroll
        for (int p = 0; p < 4; p++) {
            int i = p * 256 + tid;
            int rr = i >> 4;
            int k4 = i & 15;
            float4 v = *(const float4*)(Ak + (long)(row0 + rr) * ldak + kb + k4 * 4);
            *(float4*)(sA + rr * 68 + k4 * 4) = v;
        }
        if (!wtrans) {
#pragma unroll
            for (int p = 0; p < 16; p++) {
                int i = p * 256 + tid;
                int kk = i >> 6, cc = i & 63;
                sW[kk * 68 + cc] = W[(long)(k0 + kk) * ldw + col0 + cc];
            }
        } else {
#pragma unroll
            for (int p = 0; p < 16; p++) {
                int i = p * 256 + tid;
                int kk = i & 63, cc = i >> 6;
                sW[kk * 68 + cc] = W[(long)(col0 + cc) * ldw + k0 + kk];
            }
        }
        __syncthreads();

#pragma unroll
        for (int k = 0; k < 64; k++) {
            float a0 = sA[(ty * 4 + 0) * 68 + k];
            float a1 = sA[(ty * 4 + 1) * 68 + k];
            float a2 = sA[(ty * 4 + 2) * 68 + k];
            float a3 = sA[(ty * 4 + 3) * 68 + k];
            float4 wv = *(const float4*)(sW + k * 68 + tx * 4);
            acc[0][0] = fmaf(a0, wv.x, acc[0][0]);
            acc[0][1] = fmaf(a0, wv.y, acc[0][1]);
            acc[0][2] = fmaf(a0, wv.z, acc[0][2]);
            acc[0][3] = fmaf(a0, wv.w, acc[0][3]);
            acc[1][0] = fmaf(a1, wv.x, acc[1][0]);
            acc[1][1] = fmaf(a1, wv.y, acc[1][1]);
            acc[1][2] = fmaf(a1, wv.z, acc[1][2]);
            acc[1][3] = fmaf(a1, wv.w, acc[1][3]);
            acc[2][0] = fmaf(a2, wv.x, acc[2][0]);
            acc[2][1] = fmaf(a2, wv.y, acc[2][1]);
            acc[2][2] = fmaf(a2, wv.z, acc[2][2]);
            acc[2][3] = fmaf(a2, wv.w, acc[2][3]);
            acc[3][0] = fmaf(a3, wv.x, acc[3][0]);
            acc[3][1] = fmaf(a3, wv.y, acc[3][1]);
            acc[3][2] = fmaf(a3, wv.z, acc[3][2]);
            acc[3][3] = fmaf(a3, wv.w, acc[3][3]);
        }
    }

#pragma unroll
    for (int i = 0; i < 4; i++) {
#pragma unroll
        for (int j = 0; j < 4; j++) {
            int rr = row0 + ty * 4 + i;
            int cc = col0 + tx * 4 + j;
            float v = acc[i][j] + bias[cc];
            if (act) v = tanhf(v);
            C[(long)rr * ldc + cc] = v;
        }
    }
}

// ---------------- K1: precompute pre1[t] = x_t @ Wih_f[0,t] + b_f[0,t] ----------------
__global__ __launch_bounds__(256) void k_pre(
    const float* __restrict__ x, const float* __restrict__ Wih_f,
    const float* __restrict__ b_f)
{
    __shared__ float sA[64 * 68];
    __shared__ float sW[64 * 68];
    int t = blockIdx.y;
    int tile = blockIdx.x;
    int row0 = (tile >> 2) * 64;
    int col0 = (tile & 3) * 64;
    gemm64_body(x + (long)t * DD, (long)TT * DD,
                nullptr, 1 << 30, 0,
                Wih_f + (long)t * DD * HH, HH, 0,
                b_f + (long)t * HH,
                g_pre1 + (long)t * BB * HH, HH,
                DD, row0, col0, /*act=*/0, sA, sW);
}

// ================= K2: persistent sequential scan =================
// CTA tile: batch rows [8g, 8g+8) x cols [32r, 32r+32)  (g = bx>>3, r = bx&7).
// Thread (s = tid>>5 k-slice, c = tid&31 column). Weights in registers
// (coalesced LDG, prefetched during previous phase's compute); h loads from
// shared are warp-uniform broadcasts (conflict-free, 1 cyc). Split-K reduced
// through smem. Sync = monotonic atomic-counter grid barrier (round-1
// mechanism; no L1-flushing cluster.sync, no per-phase membar storm).

// ---------------- grid barrier (monotonic counter, reset per replay) ----------------
__device__ __forceinline__ void grid_barrier(unsigned idx) {
    __syncthreads();
    __threadfence();
    if (threadIdx.x == 0) {
        atomicAdd(&g_cnt, 1u);
        unsigned target = idx * (unsigned)NBLK;
        while (*((volatile unsigned*)&g_cnt) < target) __nanosleep(16);
        __threadfence();
    }
    __syncthreads();
}

__device__ __forceinline__ void stage_hs(float* hs, const float* __restrict__ src,
                                         int row_base, int tid) {
#pragma unroll
    for (int p = 0; p < 2; p++) {
        int i = p * 256 + tid;
        int rr = i >> 6;
        int c4 = i & 63;
        float4 v = __ldcg((const float4*)(src + (long)(row_base + rr) * HH) + c4);
        *((float4*)(hs + rr * HH) + c4) = v;
    }
}

// prefetch weight slice: w[j] = W[(32s+j)][col0+c]  (coalesced across warp per j)
__device__ __forceinline__ void pf_w(float (&w)[32], const float* __restrict__ W,
                                     int s, int c, int col0) {
    const float* p = W + (long)(s * 32) * HH + col0 + c;
#pragma unroll
    for (int j = 0; j < 32; j++) w[j] = __ldg(p + (long)j * HH);
}

__device__ __forceinline__ void compute_dot(const float* hs, const float (&w)[32],
                                            int s, float (&acc)[8]) {
#pragma unroll
    for (int r = 0; r < 8; r++) acc[r] = 0.f;
#pragma unroll
    for (int i = 0; i < 8; i++) {
        float4 hv[8];
#pragma unroll
        for (int r = 0; r < 8; r++)
            hv[r] = *((const float4*)(hs + r * HH + s * 32 + i * 4));  // uniform bcast
#pragma unroll
        for (int r = 0; r < 8; r++) {
            acc[r] = fmaf(hv[r].x, w[i * 4 + 0], acc[r]);
            acc[r] = fmaf(hv[r].y, w[i * 4 + 1], acc[r]);
            acc[r] = fmaf(hv[r].z, w[i * 4 + 2], acc[r]);
            acc[r] = fmaf(hv[r].w, w[i * 4 + 3], acc[r]);
        }
    }
}

__device__ __forceinline__ float reduce_partials(float* red, const float (&acc)[8],
                                                 int s, int c) {
#pragma unroll
    for (int r = 0; r < 8; r++) red[s * 256 + r * 32 + c] = acc[r];
    __syncthreads();
    // thread's output element: row = s, col = c (within block tile)
    float v = 0.f;
#pragma unroll
    for (int q = 0; q < 8; q++) v += red[q * 256 + s * 32 + c];
    return v;
}

// one dot phase: stage h rows, prefetch next weights, compute, split-K reduce
__device__ __forceinline__ float phase_dot(
    float* hs, float* red,
    const float* __restrict__ h_src, int row_base,
    const float (&wu)[32], float (&wp)[32], const float* __restrict__ pfW,
    int s, int c, int col0, int tid)
{
    stage_hs(hs, h_src, row_base, tid);
    __syncthreads();                   // also protects red[] reads of prior phase
    pf_w(wp, pfW, s, c, col0);         // overlap prefetch with compute
    float acc[8];
    compute_dot(hs, wu, s, acc);
    return reduce_partials(red, acc, s, c);
}

__global__ __launch_bounds__(256, 1)
void k_seq(const float* __restrict__ Wih_f, const float* __restrict__ Whh_f,
           const float* __restrict__ b_f)
{
    __shared__ float hs[8 * HH];      // 8 KB
    __shared__ float red[8 * 256];    // 8 KB
    const int tid = threadIdx.x;
    const int s = tid >> 5;
    const int c = tid & 31;
    const int grp = blockIdx.x >> 3;
    const int rank = blockIdx.x & 7;
    const int row_base = grp * 8;
    const int col0 = rank * 32;
    const int out_off = (row_base + s) * HH + col0 + c;

    const float* Whh1 = Whh_f;
    const float* Wih2 = Wih_f + (long)TT * DD * HH;
    const float* Whh2 = Whh_f + (long)TT * HH * HH;
    const float* b2   = b_f + (long)TT * HH;

    float wX[32], wY[32];
    pf_w(wX, Whh1, s, c, col0);       // Whh1[t=0]
    unsigned bar = 0;

#define STEP(WA, WB, t, pp)                                                         \
    {                                                                               \
        int tn = (t) < TT - 1 ? (t) + 1 : TT - 1;                                   \
        /* phase A: h1_new = tanh(pre1[t] + h1_prev @ Whh1[t]) */                   \
        float dA = phase_dot(hs, red, g_h1[pp], row_base, WA, WB,                   \
                             Wih2 + (long)(t) * DD * HH, s, c, col0, tid);          \
        float pre = __ldg(g_pre1 + (long)(t) * BB * HH + out_off);                  \
        float h1v = tanhf(pre + dA);                                                \
        __stcg(g_h1[(pp) ^ 1] + out_off, h1v);                                      \
        grid_barrier(++bar);                                                        \
        /* phase B1: acc2 = b2[t] + h1_new @ Wih2[t] */                             \
        float d1 = phase_dot(hs, red, g_h1[(pp) ^ 1], row_base, WB, WA,             \
                             Whh2 + (long)(t) * HH * HH, s, c, col0, tid);          \
        float acc2 = __ldg(b2 + (long)(t) * HH + col0 + c) + d1;                    \
        /* phase B2: acc2 += h2_prev @ Whh2[t] */                                   \
        float d2 = phase_dot(hs, red, g_h2[pp], row_base, WA, WB,                   \
                             Whh1 + (long)tn * HH * HH, s, c, col0, tid);           \
        acc2 += d2;                                                                 \
        float h2v = tanhf(acc2);                                                    \
        __stcg(g_h2[(pp) ^ 1] + out_off, h2v);                                      \
        grid_barrier(++bar);                                                        \
    }

#pragma unroll 1
    for (int t2 = 0; t2 < TT; t2 += 2) {
        STEP(wX, wY, t2, 0);          // t even: pp = 0
        STEP(wY, wX, t2 + 1, 1);      // t odd:  pp = 1
    }
#undef STEP
}

// ---------------- tail kernels: backward single step + fc head ----------------
__global__ __launch_bounds__(256) void k_tail_a(
    const float* __restrict__ x, const float* __restrict__ Wih_b,
    const float* __restrict__ b_b)
{
    __shared__ float sA[64 * 68];
    __shared__ float sW[64 * 68];
    int tile = blockIdx.x;
    int row0 = (tile >> 2) * 64, col0 = (tile & 3) * 64;
    gemm64_body(x + (long)(TT - 1) * DD, (long)TT * DD,
                nullptr, 1 << 30, 0,
                Wih_b + (long)(TT - 1) * DD * HH, HH, 0,
                b_b + (long)(TT - 1) * HH,
                g_h1bk, HH, DD, row0, col0, /*act=*/1, sA, sW);
}

__global__ __launch_bounds__(256) void k_tail_b(
    const float* __restrict__ Wih_b, const float* __restrict__ b_b)
{
    __shared__ float sA[64 * 68];
    __shared__ float sW[64 * 68];
    int tile = blockIdx.x;
    int row0 = (tile >> 2) * 64, col0 = (tile & 3) * 64;
    gemm64_body(g_h1bk, HH,
                nullptr, 1 << 30, 0,
                Wih_b + (long)(TT + TT - 1) * DD * HH, HH, 0,
                b_b + (long)(TT + TT - 1) * HH,
                g_h2bk, HH, HH, row0, col0, /*act=*/1, sA, sW);
}

__global__ __launch_bounds__(256) void k_tail_c(
    const float* __restrict__ fc_w, const float* __restrict__ fc_b,
    float* __restrict__ out)
{
    __shared__ float sA[64 * 68];
    __shared__ float sW[64 * 68];
    int tile = blockIdx.x;
    int row0 = (tile >> 2) * 64, col0 = (tile & 3) * 64;
    // h2 forward final state lives in g_h2[0] (T=256 even)
    gemm64_body(g_h2[0], HH,
                g_h2bk, /*ksplit=*/HH, HH,
                fc_w, 2 * HH, /*wtrans=*/1,
                fc_b,
                out, HH, 2 * HH, row0, col0, /*act=*/0, sA, sW);
}

// ---------------- launcher ----------------
extern "C" void kernel_launch(void* const* d_in, const int* in_sizes, int n_in,
                              void* d_out, int out_size) {
    const float* x     = (const float*)d_in[0];
    const float* Wih_f = (const float*)d_in[1];
    const float* Whh_f = (const float*)d_in[2];
    const float* b_f   = (const float*)d_in[3];
    const float* Wih_b = (const float*)d_in[4];
    // d_in[5] = Whh_b: unused (backward output at t=T-1 starts from h0=0)
    const float* b_b   = (const float*)d_in[6];
    const float* fc_w  = (const float*)d_in[7];
    const float* fc_b  = (const float*)d_in[8];
    float* out = (float*)d_out;
    (void)in_sizes; (void)n_in; (void)out_size;

    k_reset<<<32, 256>>>();
    k_pre<<<dim3(8, TT), 256>>>(x, Wih_f, b_f);
    k_seq<<<NBLK, 256>>>(Wih_f, Whh_f, b_f);
    k_tail_a<<<8, 256>>>(x, Wih_b, b_b);
    k_tail_b<<<8, 256>>>(Wih_b, b_b);
    k_tail_c<<<8, 256>>>(fc_w, fc_b, out);
}